// round 10
// baseline (speedup 1.0000x reference)
#include <cuda_runtime.h>
#include <math_constants.h>

#define NROWS 8192
#define IN_DIM 128
#define HID 256
#define SLOPE 0.01f
#define S_CONST 8192.0f

// ---------------- scratch (__device__ globals; no allocs allowed) ----------
__device__ __align__(16) float g_Ppart[32 * 256 * HID];  // [r][kb][c] split-K partials (8 MB)
__device__ __align__(16) float g_v[NROWS];               // normalized flat[:8192]
__device__ __align__(16) float g_Upart[32 * IN_DIM];     // per-v-row partials of v^T X

// ---------------- kernel A (fused): H-rows in registers -> Ep partials -----
// grid 256 blocks (32 rows each), 256 threads.
// GEMM mapping: lane = row (32 rows), warp cg = 32-column group.
//   -> W[col][k4] is warp-uniform (broadcast LDG, 1 wavefront)
//   -> X row read is one lane-strided LDS.128 per k4 (padded, conflict-free)
// h staged through padded smem, then the R7 Ep loop (thread = column).
__global__ void __launch_bounds__(256) k_zhe(
        const float* __restrict__ X, const float* __restrict__ W,
        const float* __restrict__ b, const float* __restrict__ E,
        const float* __restrict__ Ai, const float* __restrict__ Aj) {
    __shared__ float4 Xs4[32 * 33];              // 32 rows x 32 float4, pad 1
    __shared__ __align__(16) float Es[32][32];   // [kk][r]: broadcast float4 reads
    __shared__ float Hs[32 * 257];               // [row][col], pad 1 float
    __shared__ float sred[128];
    const int t    = threadIdx.x;
    const int lane = t & 31;
    const int cg   = t >> 5;                     // warp id = column group
    const int r0   = blockIdx.x * 32;            // row base == E k-chunk base

    if (t < 128) sred[t] = Ai[t] + Aj[t];

    {   // X tile (padded rows)
        const float4* X4 = (const float4*)(X + (size_t)r0 * IN_DIM);
        for (int i = t; i < 32 * 32; i += 256) {
            int r = i >> 5, k4 = i & 31;
            Xs4[r * 33 + k4] = X4[i];
        }
    }
    // E tile: rows 0..31, cols r0..r0+31, layout [kk][r]
    for (int i = t; i < 32 * 32; i += 256) {
        int r = i & 31, kk = i >> 5;
        Es[kk][r] = E[(size_t)r * NROWS + r0 + kk];
    }
    __syncthreads();

    // finish s-reduction
    if (t < 64) sred[t] += sred[t + 64];
    __syncthreads();
    if (t < 32) {
        float x = sred[t] + sred[t + 32];
#pragma unroll
        for (int o = 16; o > 0; o >>= 1) x += __shfl_xor_sync(0xffffffffu, x, o);
        if (t == 0) sred[0] = x;
    }
    __syncthreads();
    const float s = sred[0];

    // ---- GEMM: acc[c] = X[r0+lane,:] . W[32cg+c,:] ----
    float acc[32];
#pragma unroll
    for (int c = 0; c < 32; c++) acc[c] = 0.f;

    const float4* Wb = ((const float4*)W) + (size_t)(cg * 32) * 32;  // 32 float4 per col
#pragma unroll 1
    for (int k4 = 0; k4 < 32; k4++) {
        float4 xv = Xs4[lane * 33 + k4];         // lane-strided, conflict-free
        const float4* wp = Wb + k4;
#pragma unroll
        for (int c = 0; c < 32; c++) {
            float4 wv = wp[c * 32];              // warp-uniform broadcast LDG
            acc[c] += xv.x * wv.x + xv.y * wv.y + xv.z * wv.z + xv.w * wv.w;
        }
    }

    // ---- activation; stage h into padded smem ----
#pragma unroll
    for (int c = 0; c < 32; c++) {
        float a  = (acc[c] + b[cg * 32 + c]) * s;
        float lr = a > 0.f ? a : SLOPE * a;
        Hs[lane * 257 + cg * 32 + c] = __expf(lr);   // bank (lane+col)%32: conflict-free
    }
    __syncthreads();

    // ---- Ep partial (R7 loop): thread t = column; acc2[r] = sum_kk E[r][kk]*h[kk][t]
    float acc2[32];
#pragma unroll
    for (int r = 0; r < 32; r++) acc2[r] = 0.f;

#pragma unroll 4
    for (int kk = 0; kk < 32; kk++) {
        float h = Hs[kk * 257 + t];              // consecutive lanes: conflict-free
        const float4* es4 = (const float4*)Es[kk];
#pragma unroll
        for (int r4 = 0; r4 < 8; r4++) {
            float4 e = es4[r4];
            acc2[r4 * 4 + 0] += e.x * h;
            acc2[r4 * 4 + 1] += e.y * h;
            acc2[r4 * 4 + 2] += e.z * h;
            acc2[r4 * 4 + 3] += e.w * h;
        }
    }
#pragma unroll
    for (int r = 0; r < 32; r++)
        g_Ppart[((size_t)r * 256 + blockIdx.x) * HID + t] = acc2[r];
}

// ---------------- kernel B: reduce partials -> v; also partial of v^T X ----
// grid 32 blocks (one v-row each), 1024 threads
__global__ void k_v(const float* __restrict__ X) {
    __shared__ float sm[16][256];
    __shared__ float red[256];
    __shared__ float vsm[256];
    __shared__ float su[8][128];
    const int t = threadIdx.x;
    const int r = blockIdx.x;

    {   // phase 1: sum 256 kb-partials (contiguous, float4)
        const float4* P4 = (const float4*)(g_Ppart + (size_t)r * 256 * HID);
        const int c4 = t & 63, y = t >> 6;
        float4 a = make_float4(0.f, 0.f, 0.f, 0.f);
#pragma unroll
        for (int m = 0; m < 16; m++) {
            float4 p = P4[(size_t)(y + 16 * m) * 64 + c4];
            a.x += p.x; a.y += p.y; a.z += p.z; a.w += p.w;
        }
        sm[y][c4 * 4 + 0] = a.x;
        sm[y][c4 * 4 + 1] = a.y;
        sm[y][c4 * 4 + 2] = a.z;
        sm[y][c4 * 4 + 3] = a.w;
    }
    __syncthreads();

    float p = 0.f;
    if (t < 256) {
#pragma unroll
        for (int y = 0; y < 16; y++) p += sm[y][t];
        red[t] = p;
    }
    __syncthreads();
    if (t < 128) red[t] += red[t + 128];
    __syncthreads();
    if (t < 64)  red[t] += red[t + 64];
    __syncthreads();
    if (t < 32) {
        float x = red[t] + red[t + 32];
#pragma unroll
        for (int o = 16; o > 0; o >>= 1) x += __shfl_xor_sync(0xffffffffu, x, o);
        if (t == 0) red[0] = x;
    }
    __syncthreads();
    const float inv = 1.0f / red[0];
    if (t < 256) {
        float v = p * inv;
        vsm[t] = v;
        g_v[r * HID + t] = v;
    }
    __syncthreads();

    {   // phase 2: partial t_r[k] = sum_{c<256} v_c * X[256r + c][k]
        const int k = t & 127, jg = t >> 7;     // jg in [0,8)
        float acc = 0.f;
        const float* Xr = X + ((size_t)r * 256 + jg * 32) * IN_DIM + k;
#pragma unroll
        for (int jj = 0; jj < 32; jj++)
            acc += vsm[jg * 32 + jj] * Xr[(size_t)jj * IN_DIM];
        su[jg][k] = acc;
    }
    __syncthreads();
    if (t < 128) {
        float tot = 0.f;
#pragma unroll
        for (int g = 0; g < 8; g++) tot += su[g][t];
        g_Upart[r * IN_DIM + t] = tot;
    }
}

// ---------------- kernel C (fused): out blocks + alpha blocks --------------
// grid = 64 + 8192, 256 threads.
//   bid < 64   : redundant-w + softmax for 128 rows (hides under alpha's DRAM wall)
//   bid >= 64  : alpha[bid-64,:] = (v_i/S) * v
__global__ void k_final(const float* __restrict__ W, const float* __restrict__ b,
                        float* __restrict__ out, float* __restrict__ alpha) {
    const int t = threadIdx.x;

    if (blockIdx.x < 64) {
        // ---- out path: recompute w from g_Upart (L2-cached), then softmax ----
        __shared__ __align__(16) float ts[128];
        __shared__ float ws[256];

        if (t < 128) {
            float a = 0.f;
#pragma unroll
            for (int rr = 0; rr < 32; rr++) a += g_Upart[rr * IN_DIM + t];
            ts[t] = a;
        }
        __syncthreads();

        {   // w[t] = dot(ts, W[t,:]) / S
            const float4* Wr = (const float4*)(W + (size_t)t * IN_DIM);
            const float4* t4 = (const float4*)ts;
            float d = 0.f;
#pragma unroll
            for (int i = 0; i < 32; i++) {
                float4 wv = Wr[i], tv = t4[i];
                d += wv.x * tv.x + wv.y * tv.y + wv.z * tv.z + wv.w * tv.w;
            }
            ws[t] = d * (1.0f / S_CONST);
        }
        __syncthreads();

        const int lane = t & 31, wid = t >> 5;
        const int rbase = blockIdx.x * 128 + wid * 16;

        float wl[8], bl[8];
#pragma unroll
        for (int q = 0; q < 8; q++) {
            wl[q] = ws[lane + 32 * q];
            bl[q] = b[lane + 32 * q];
        }

        for (int rr = 0; rr < 16; rr++) {
            const int i = rbase + rr;
            const float vi = g_v[i];
            float l[8];
            float m = -CUDART_INF_F;
#pragma unroll
            for (int q = 0; q < 8; q++) {
                l[q] = vi * wl[q] + bl[q];
                m = fmaxf(m, l[q]);
            }
#pragma unroll
            for (int o = 16; o > 0; o >>= 1) m = fmaxf(m, __shfl_xor_sync(0xffffffffu, m, o));
            float sum = 0.f;
#pragma unroll
            for (int q = 0; q < 8; q++) { l[q] = __expf(l[q] - m); sum += l[q]; }
#pragma unroll
            for (int o = 16; o > 0; o >>= 1) sum += __shfl_xor_sync(0xffffffffu, sum, o);
            const float inv = 1.0f / sum;
#pragma unroll
            for (int q = 0; q < 8; q++)
                out[(size_t)i * HID + lane + 32 * q] = l[q] * inv;
        }
    } else {
        // ---- alpha path: one row per block ----
        const int i = blockIdx.x - 64;
        const float a = g_v[i] * (1.0f / S_CONST);
        const float4* v4 = (const float4*)g_v;
        float4* o4 = (float4*)(alpha + (size_t)i * NROWS);
#pragma unroll
        for (int it = 0; it < 8; it++) {
            float4 vv = v4[t + 256 * it];
            o4[t + 256 * it] = make_float4(a * vv.x, a * vv.y, a * vv.z, a * vv.w);
        }
    }
}

// ---------------- launch ---------------------------------------------------
extern "C" void kernel_launch(void* const* d_in, const int* in_sizes, int n_in,
                              void* d_out, int out_size) {
    const float* X  = (const float*)d_in[0];
    const float* E  = (const float*)d_in[1];
    const float* W  = (const float*)d_in[2];
    const float* b  = (const float*)d_in[3];
    const float* Ai = (const float*)d_in[4];
    const float* Aj = (const float*)d_in[5];

    float* out   = (float*)d_out;                       // (8192, 256)
    float* alpha = out + (size_t)NROWS * HID;           // (8192, 8192)

    k_zhe  <<<256, 256>>>(X, W, b, E, Ai, Aj);
    k_v    <<<32, 1024>>>(X);
    k_final<<<64 + NROWS, 256>>>(W, b, out, alpha);
}

// round 11
// speedup vs baseline: 1.1954x; 1.1954x over previous
#include <cuda_runtime.h>
#include <math_constants.h>

#define NROWS 8192
#define IN_DIM 128
#define HID 256
#define SLOPE 0.01f
#define S_CONST 8192.0f

// ---------------- scratch (__device__ globals; no allocs allowed) ----------
__device__ __align__(16) float g_Ppart[32 * 256 * HID];  // [r][kb][c] split-K partials (8 MB)
__device__ __align__(16) float g_v[NROWS];               // normalized flat[:8192]
__device__ __align__(16) float g_Upart[32 * IN_DIM];     // per-v-row partials of v^T X

// ---------------- kernel A (fused): register-tiled GEMM -> Ep partials -----
// grid 256 blocks (32 rows each), 256 threads.
// GEMM: thread (ty,tx) = (t>>5, t&31) owns a 4-row x 8-col output tile.
//   X staged in smem [row][k] (pad 132); W staged in smem TRANSPOSED
//   [k][col] (pad 257) in four 32-k chunks. Mainloop: per k-quad,
//   4 broadcast LDS.128 (X) + 32 conflict-free LDS.32 (W) per 128 FFMA.
// Then activation in registers -> Hs (aliases Ws buffer) -> R7 Ep loop.
__global__ void __launch_bounds__(256) k_zhe(
        const float* __restrict__ X, const float* __restrict__ W,
        const float* __restrict__ b, const float* __restrict__ E,
        const float* __restrict__ Ai, const float* __restrict__ Aj) {
    __shared__ float Xs[32 * 132];               // [row][k], pitch 132 (16B-aligned)
    __shared__ __align__(16) float Es[32][32];   // [kk][r]: broadcast float4 reads
    __shared__ __align__(16) float WsHs[32 * 257]; // Ws chunk [k][col] / later Hs [row][col]
    __shared__ float sred[128];
    const int t  = threadIdx.x;
    const int tx = t & 31;
    const int ty = t >> 5;                       // 0..7
    const int r0 = blockIdx.x * 32;              // row base == E k-chunk base

    if (t < 128) sred[t] = Ai[t] + Aj[t];

    {   // X tile: [row][k], pitch 132 floats; float4 loads, float4 stores
        const float4* X4 = (const float4*)(X + (size_t)r0 * IN_DIM);
        for (int i = t; i < 32 * 32; i += 256) {
            int r = i >> 5, k4 = i & 31;
            *(float4*)&Xs[r * 132 + k4 * 4] = X4[i];
        }
    }
    // E tile: rows 0..31, cols r0..r0+31, layout [kk][r]
    for (int i = t; i < 32 * 32; i += 256) {
        int r = i & 31, kk = i >> 5;
        Es[kk][r] = E[(size_t)r * NROWS + r0 + kk];
    }
    __syncthreads();

    // finish s-reduction
    if (t < 64) sred[t] += sred[t + 64];
    __syncthreads();
    if (t < 32) {
        float x = sred[t] + sred[t + 32];
#pragma unroll
        for (int o = 16; o > 0; o >>= 1) x += __shfl_xor_sync(0xffffffffu, x, o);
        if (t == 0) sred[0] = x;
    }
    __syncthreads();
    const float s = sred[0];

    // ---- GEMM: acc[rr][q] = X[r0 + ty*4+rr,:] . W[tx + 32q,:] ----
    float acc[4][8];
#pragma unroll
    for (int rr = 0; rr < 4; rr++)
#pragma unroll
        for (int q = 0; q < 8; q++) acc[rr][q] = 0.f;

#pragma unroll 1
    for (int kc = 0; kc < 4; kc++) {
        // stage W chunk transposed: WsHs[k_local][col], pitch 257
        __syncthreads();   // previous chunk fully consumed
        {
            // warp wg loads cols {wg, wg+8, ...}; lane = k_local (coalesced LDG,
            // conflict-free STS: lane stride 257 words)
            const float* Wsrc = W + kc * 32 + tx;
#pragma unroll 4
            for (int col = ty; col < 256; col += 8)
                WsHs[tx * 257 + col] = Wsrc[(size_t)col * IN_DIM];
        }
        __syncthreads();

        const float* Xrow = Xs + kc * 32;
#pragma unroll 2
        for (int kl = 0; kl < 32; kl += 4) {
            float4 xv[4];
#pragma unroll
            for (int rr = 0; rr < 4; rr++)
                xv[rr] = *(const float4*)&Xrow[(ty * 4 + rr) * 132 + kl]; // broadcast

#pragma unroll
            for (int kk = 0; kk < 4; kk++) {
                float wv[8];
                const float* wrow = &WsHs[(kl + kk) * 257 + tx];
#pragma unroll
                for (int q = 0; q < 8; q++) wv[q] = wrow[q * 32];  // conflict-free
#pragma unroll
                for (int rr = 0; rr < 4; rr++) {
                    float xk = (kk == 0) ? xv[rr].x : (kk == 1) ? xv[rr].y
                             : (kk == 2) ? xv[rr].z : xv[rr].w;
#pragma unroll
                    for (int q = 0; q < 8; q++)
                        acc[rr][q] += xk * wv[q];
                }
            }
        }
    }

    // ---- activation; stage h into Hs (aliases Ws buffer) ----
    __syncthreads();                 // Ws no longer needed
    {
        float bq[8];
#pragma unroll
        for (int q = 0; q < 8; q++) bq[q] = b[tx + 32 * q];
#pragma unroll
        for (int rr = 0; rr < 4; rr++) {
#pragma unroll
            for (int q = 0; q < 8; q++) {
                float a  = (acc[rr][q] + bq[q]) * s;
                float lr = a > 0.f ? a : SLOPE * a;
                WsHs[(ty * 4 + rr) * 257 + tx + 32 * q] = __expf(lr);
            }
        }
    }
    __syncthreads();

    // ---- Ep partial (R7 loop): thread t = column; acc2[r] = sum_kk E[r][kk]*h[kk][t]
    float acc2[32];
#pragma unroll
    for (int r = 0; r < 32; r++) acc2[r] = 0.f;

#pragma unroll 4
    for (int kk = 0; kk < 32; kk++) {
        float h = WsHs[kk * 257 + t];            // consecutive lanes: conflict-free
        const float4* es4 = (const float4*)Es[kk];
#pragma unroll
        for (int r4 = 0; r4 < 8; r4++) {
            float4 e = es4[r4];
            acc2[r4 * 4 + 0] += e.x * h;
            acc2[r4 * 4 + 1] += e.y * h;
            acc2[r4 * 4 + 2] += e.z * h;
            acc2[r4 * 4 + 3] += e.w * h;
        }
    }
#pragma unroll
    for (int r = 0; r < 32; r++)
        g_Ppart[((size_t)r * 256 + blockIdx.x) * HID + t] = acc2[r];
}

// ---------------- kernel B: reduce partials -> v; also partial of v^T X ----
// grid 32 blocks (one v-row each), 1024 threads
__global__ void k_v(const float* __restrict__ X) {
    __shared__ float sm[16][256];
    __shared__ float red[256];
    __shared__ float vsm[256];
    __shared__ float su[8][128];
    const int t = threadIdx.x;
    const int r = blockIdx.x;

    {   // phase 1: sum 256 kb-partials (contiguous, float4)
        const float4* P4 = (const float4*)(g_Ppart + (size_t)r * 256 * HID);
        const int c4 = t & 63, y = t >> 6;
        float4 a = make_float4(0.f, 0.f, 0.f, 0.f);
#pragma unroll
        for (int m = 0; m < 16; m++) {
            float4 p = P4[(size_t)(y + 16 * m) * 64 + c4];
            a.x += p.x; a.y += p.y; a.z += p.z; a.w += p.w;
        }
        sm[y][c4 * 4 + 0] = a.x;
        sm[y][c4 * 4 + 1] = a.y;
        sm[y][c4 * 4 + 2] = a.z;
        sm[y][c4 * 4 + 3] = a.w;
    }
    __syncthreads();

    float p = 0.f;
    if (t < 256) {
#pragma unroll
        for (int y = 0; y < 16; y++) p += sm[y][t];
        red[t] = p;
    }
    __syncthreads();
    if (t < 128) red[t] += red[t + 128];
    __syncthreads();
    if (t < 64)  red[t] += red[t + 64];
    __syncthreads();
    if (t < 32) {
        float x = red[t] + red[t + 32];
#pragma unroll
        for (int o = 16; o > 0; o >>= 1) x += __shfl_xor_sync(0xffffffffu, x, o);
        if (t == 0) red[0] = x;
    }
    __syncthreads();
    const float inv = 1.0f / red[0];
    if (t < 256) {
        float v = p * inv;
        vsm[t] = v;
        g_v[r * HID + t] = v;
    }
    __syncthreads();

    {   // phase 2: partial t_r[k] = sum_{c<256} v_c * X[256r + c][k]
        const int k = t & 127, jg = t >> 7;     // jg in [0,8)
        float acc = 0.f;
        const float* Xr = X + ((size_t)r * 256 + jg * 32) * IN_DIM + k;
#pragma unroll
        for (int jj = 0; jj < 32; jj++)
            acc += vsm[jg * 32 + jj] * Xr[(size_t)jj * IN_DIM];
        su[jg][k] = acc;
    }
    __syncthreads();
    if (t < 128) {
        float tot = 0.f;
#pragma unroll
        for (int g = 0; g < 8; g++) tot += su[g][t];
        g_Upart[r * IN_DIM + t] = tot;
    }
}

// ---------------- kernel C (fused): out blocks + alpha blocks --------------
// grid = 64 + 8192, 256 threads.
//   bid < 64   : redundant-w + softmax for 128 rows (hides under alpha's DRAM wall)
//   bid >= 64  : alpha[bid-64,:] = (v_i/S) * v
__global__ void k_final(const float* __restrict__ W, const float* __restrict__ b,
                        float* __restrict__ out, float* __restrict__ alpha) {
    const int t = threadIdx.x;

    if (blockIdx.x < 64) {
        // ---- out path: recompute w from g_Upart (L2-cached), then softmax ----
        __shared__ __align__(16) float ts[128];
        __shared__ float ws[256];

        if (t < 128) {
            float a = 0.f;
#pragma unroll
            for (int rr = 0; rr < 32; rr++) a += g_Upart[rr * IN_DIM + t];
            ts[t] = a;
        }
        __syncthreads();

        {   // w[t] = dot(ts, W[t,:]) / S
            const float4* Wr = (const float4*)(W + (size_t)t * IN_DIM);
            const float4* t4 = (const float4*)ts;
            float d = 0.f;
#pragma unroll
            for (int i = 0; i < 32; i++) {
                float4 wv = Wr[i], tv = t4[i];
                d += wv.x * tv.x + wv.y * tv.y + wv.z * tv.z + wv.w * tv.w;
            }
            ws[t] = d * (1.0f / S_CONST);
        }
        __syncthreads();

        const int lane = t & 31, wid = t >> 5;
        const int rbase = blockIdx.x * 128 + wid * 16;

        float wl[8], bl[8];
#pragma unroll
        for (int q = 0; q < 8; q++) {
            wl[q] = ws[lane + 32 * q];
            bl[q] = b[lane + 32 * q];
        }

        for (int rr = 0; rr < 16; rr++) {
            const int i = rbase + rr;
            const float vi = g_v[i];
            float l[8];
            float m = -CUDART_INF_F;
#pragma unroll
            for (int q = 0; q < 8; q++) {
                l[q] = vi * wl[q] + bl[q];
                m = fmaxf(m, l[q]);
            }
#pragma unroll
            for (int o = 16; o > 0; o >>= 1) m = fmaxf(m, __shfl_xor_sync(0xffffffffu, m, o));
            float sum = 0.f;
#pragma unroll
            for (int q = 0; q < 8; q++) { l[q] = __expf(l[q] - m); sum += l[q]; }
#pragma unroll
            for (int o = 16; o > 0; o >>= 1) sum += __shfl_xor_sync(0xffffffffu, sum, o);
            const float inv = 1.0f / sum;
#pragma unroll
            for (int q = 0; q < 8; q++)
                out[(size_t)i * HID + lane + 32 * q] = l[q] * inv;
        }
    } else {
        // ---- alpha path: one row per block ----
        const int i = blockIdx.x - 64;
        const float a = g_v[i] * (1.0f / S_CONST);
        const float4* v4 = (const float4*)g_v;
        float4* o4 = (float4*)(alpha + (size_t)i * NROWS);
#pragma unroll
        for (int it = 0; it < 8; it++) {
            float4 vv = v4[t + 256 * it];
            o4[t + 256 * it] = make_float4(a * vv.x, a * vv.y, a * vv.z, a * vv.w);
        }
    }
}

// ---------------- launch ---------------------------------------------------
extern "C" void kernel_launch(void* const* d_in, const int* in_sizes, int n_in,
                              void* d_out, int out_size) {
    const float* X  = (const float*)d_in[0];
    const float* E  = (const float*)d_in[1];
    const float* W  = (const float*)d_in[2];
    const float* b  = (const float*)d_in[3];
    const float* Ai = (const float*)d_in[4];
    const float* Aj = (const float*)d_in[5];

    float* out   = (float*)d_out;                       // (8192, 256)
    float* alpha = out + (size_t)NROWS * HID;           // (8192, 8192)

    k_zhe  <<<256, 256>>>(X, W, b, E, Ai, Aj);
    k_v    <<<32, 1024>>>(X);
    k_final<<<64 + NROWS, 256>>>(W, b, out, alpha);
}

// round 12
// speedup vs baseline: 1.2840x; 1.0741x over previous
#include <cuda_runtime.h>
#include <math_constants.h>

#define NROWS 8192
#define IN_DIM 128
#define HID 256
#define SLOPE 0.01f
#define S_CONST 8192.0f

// ---------------- scratch (__device__ globals; no allocs allowed) ----------
__device__ __align__(16) float g_Ppart[32 * 256 * HID];  // [r][kb][c] split-K partials (8 MB)
__device__ __align__(16) float g_v[NROWS];               // normalized flat[:8192]
__device__ __align__(16) float g_Upart[32 * IN_DIM];     // per-v-row partials of v^T X

// ---------------- kernel A (fused): register-tiled GEMM -> Ep partials -----
// grid 512 blocks: kb = bid>>1 (32-row chunk), ch = bid&1 (128-col half).
// 256 threads; thread (ty,tx) owns 4 rows x 4 cols. X broadcasts are
// warp-uniform; W staged transposed [k][col] pitch 129 (conflict-free).
// 512 blocks -> ~3.5 blocks/SM so FFMA issue binds instead of occupancy.
__global__ void __launch_bounds__(256) k_zhe(
        const float* __restrict__ X, const float* __restrict__ W,
        const float* __restrict__ b, const float* __restrict__ E,
        const float* __restrict__ Ai, const float* __restrict__ Aj) {
    __shared__ float Xs[32 * 132];                // [row][k], pitch 132 (16B-aligned)
    __shared__ __align__(16) float Es[32][32];    // [kk][r]: broadcast float4 reads
    __shared__ __align__(16) float WsHs[32 * 129];// Ws chunk [k][col] / later Hs [row][col]
    __shared__ float sred[128];
    const int t  = threadIdx.x;
    const int tx = t & 31;
    const int ty = t >> 5;                        // 0..7 (constant per warp)
    const int kb = blockIdx.x >> 1;
    const int ch = blockIdx.x & 1;
    const int r0 = kb * 32;                       // row base == E k-chunk base
    const int c0 = ch * 128;                      // column-half base

    if (t < 128) sred[t] = Ai[t] + Aj[t];

    {   // X tile: [row][k], pitch 132 floats; float4 loads/stores
        const float4* X4 = (const float4*)(X + (size_t)r0 * IN_DIM);
        for (int i = t; i < 32 * 32; i += 256) {
            int r = i >> 5, k4 = i & 31;
            *(float4*)&Xs[r * 132 + k4 * 4] = X4[i];
        }
    }
    // E tile: rows 0..31, cols r0..r0+31, layout [kk][r]
    for (int i = t; i < 32 * 32; i += 256) {
        int r = i & 31, kk = i >> 5;
        Es[kk][r] = E[(size_t)r * NROWS + r0 + kk];
    }
    __syncthreads();

    // finish s-reduction
    if (t < 64) sred[t] += sred[t + 64];
    __syncthreads();
    if (t < 32) {
        float x = sred[t] + sred[t + 32];
#pragma unroll
        for (int o = 16; o > 0; o >>= 1) x += __shfl_xor_sync(0xffffffffu, x, o);
        if (t == 0) sred[0] = x;
    }
    __syncthreads();
    const float s = sred[0];

    // ---- GEMM: acc[rr][q] = X[r0 + ty*4+rr,:] . W[c0 + tx + 32q,:] ----
    float acc[4][4];
#pragma unroll
    for (int rr = 0; rr < 4; rr++)
#pragma unroll
        for (int q = 0; q < 4; q++) acc[rr][q] = 0.f;

#pragma unroll 1
    for (int kc = 0; kc < 4; kc++) {
        __syncthreads();   // previous chunk fully consumed
        {   // stage W chunk transposed: WsHs[k_local][col], pitch 129
            // lane tx = k_local (coalesced LDG); STS lane-stride 129 words
            const float* Wsrc = W + (size_t)(c0) * IN_DIM + kc * 32 + tx;
#pragma unroll 4
            for (int col = ty; col < 128; col += 8)
                WsHs[tx * 129 + col] = Wsrc[(size_t)col * IN_DIM];
        }
        __syncthreads();

        const float* Xrow = Xs + kc * 32;
#pragma unroll 2
        for (int kl = 0; kl < 32; kl += 4) {
            float4 xv[4];
#pragma unroll
            for (int rr = 0; rr < 4; rr++)     // warp-uniform broadcast LDS.128
                xv[rr] = *(const float4*)&Xrow[(ty * 4 + rr) * 132 + kl];

#pragma unroll
            for (int kk = 0; kk < 4; kk++) {
                float wv[4];
                const float* wrow = &WsHs[(kl + kk) * 129 + tx];
#pragma unroll
                for (int q = 0; q < 4; q++) wv[q] = wrow[q * 32];  // conflict-free
#pragma unroll
                for (int rr = 0; rr < 4; rr++) {
                    float xk = (kk == 0) ? xv[rr].x : (kk == 1) ? xv[rr].y
                             : (kk == 2) ? xv[rr].z : xv[rr].w;
#pragma unroll
                    for (int q = 0; q < 4; q++)
                        acc[rr][q] += xk * wv[q];
                }
            }
        }
    }

    // ---- activation; stage h into Hs (aliases Ws buffer) ----
    __syncthreads();                 // Ws no longer needed
    {
        float bq[4];
#pragma unroll
        for (int q = 0; q < 4; q++) bq[q] = b[c0 + tx + 32 * q];
#pragma unroll
        for (int rr = 0; rr < 4; rr++) {
#pragma unroll
            for (int q = 0; q < 4; q++) {
                float a  = (acc[rr][q] + bq[q]) * s;
                float lr = a > 0.f ? a : SLOPE * a;
                WsHs[(ty * 4 + rr) * 129 + tx + 32 * q] = __expf(lr);
            }
        }
    }
    __syncthreads();

    // ---- Ep partial: thread t -> (col = t&127, row-half rh = t>>7) ----
    //   acc2[j] = sum_kk E[16rh+j][r0+kk] * h[kk][c0+col]
    const int col = t & 127;
    const int rh  = t >> 7;          // 0 or 1
    float acc2[16];
#pragma unroll
    for (int j = 0; j < 16; j++) acc2[j] = 0.f;

#pragma unroll 4
    for (int kk = 0; kk < 32; kk++) {
        float h = WsHs[kk * 129 + col];          // consecutive lanes: conflict-free
        const float4* es4 = (const float4*)Es[kk] + rh * 4;
#pragma unroll
        for (int j4 = 0; j4 < 4; j4++) {
            float4 e = es4[j4];
            acc2[j4 * 4 + 0] += e.x * h;
            acc2[j4 * 4 + 1] += e.y * h;
            acc2[j4 * 4 + 2] += e.z * h;
            acc2[j4 * 4 + 3] += e.w * h;
        }
    }
#pragma unroll
    for (int j = 0; j < 16; j++)
        g_Ppart[((size_t)(rh * 16 + j) * 256 + kb) * HID + c0 + col] = acc2[j];
}

// ---------------- kernel B: reduce partials -> v; also partial of v^T X ----
// grid 32 blocks (one v-row each), 1024 threads
__global__ void k_v(const float* __restrict__ X) {
    __shared__ float sm[16][256];
    __shared__ float red[256];
    __shared__ float vsm[256];
    __shared__ float su[8][128];
    const int t = threadIdx.x;
    const int r = blockIdx.x;

    {   // phase 1: sum 256 kb-partials (contiguous, float4)
        const float4* P4 = (const float4*)(g_Ppart + (size_t)r * 256 * HID);
        const int c4 = t & 63, y = t >> 6;
        float4 a = make_float4(0.f, 0.f, 0.f, 0.f);
#pragma unroll
        for (int m = 0; m < 16; m++) {
            float4 p = P4[(size_t)(y + 16 * m) * 64 + c4];
            a.x += p.x; a.y += p.y; a.z += p.z; a.w += p.w;
        }
        sm[y][c4 * 4 + 0] = a.x;
        sm[y][c4 * 4 + 1] = a.y;
        sm[y][c4 * 4 + 2] = a.z;
        sm[y][c4 * 4 + 3] = a.w;
    }
    __syncthreads();

    float p = 0.f;
    if (t < 256) {
#pragma unroll
        for (int y = 0; y < 16; y++) p += sm[y][t];
        red[t] = p;
    }
    __syncthreads();
    if (t < 128) red[t] += red[t + 128];
    __syncthreads();
    if (t < 64)  red[t] += red[t + 64];
    __syncthreads();
    if (t < 32) {
        float x = red[t] + red[t + 32];
#pragma unroll
        for (int o = 16; o > 0; o >>= 1) x += __shfl_xor_sync(0xffffffffu, x, o);
        if (t == 0) red[0] = x;
    }
    __syncthreads();
    const float inv = 1.0f / red[0];
    if (t < 256) {
        float v = p * inv;
        vsm[t] = v;
        g_v[r * HID + t] = v;
    }
    __syncthreads();

    {   // phase 2: partial t_r[k] = sum_{c<256} v_c * X[256r + c][k]
        const int k = t & 127, jg = t >> 7;     // jg in [0,8)
        float acc = 0.f;
        const float* Xr = X + ((size_t)r * 256 + jg * 32) * IN_DIM + k;
#pragma unroll
        for (int jj = 0; jj < 32; jj++)
            acc += vsm[jg * 32 + jj] * Xr[(size_t)jj * IN_DIM];
        su[jg][k] = acc;
    }
    __syncthreads();
    if (t < 128) {
        float tot = 0.f;
#pragma unroll
        for (int g = 0; g < 8; g++) tot += su[g][t];
        g_Upart[r * IN_DIM + t] = tot;
    }
}

// ---------------- kernel C (fused): out blocks + alpha blocks --------------
// grid = 64 + 8192, 256 threads.
//   bid < 64   : redundant-w + softmax for 128 rows (hides under alpha's DRAM wall)
//   bid >= 64  : alpha[bid-64,:] = (v_i/S) * v
__global__ void k_final(const float* __restrict__ W, const float* __restrict__ b,
                        float* __restrict__ out, float* __restrict__ alpha) {
    const int t = threadIdx.x;

    if (blockIdx.x < 64) {
        // ---- out path: recompute w from g_Upart (L2-cached), then softmax ----
        __shared__ __align__(16) float ts[128];
        __shared__ float ws[256];

        if (t < 128) {
            float a = 0.f;
#pragma unroll
            for (int rr = 0; rr < 32; rr++) a += g_Upart[rr * IN_DIM + t];
            ts[t] = a;
        }
        __syncthreads();

        {   // w[t] = dot(ts, W[t,:]) / S
            const float4* Wr = (const float4*)(W + (size_t)t * IN_DIM);
            const float4* t4 = (const float4*)ts;
            float d = 0.f;
#pragma unroll
            for (int i = 0; i < 32; i++) {
                float4 wv = Wr[i], tv = t4[i];
                d += wv.x * tv.x + wv.y * tv.y + wv.z * tv.z + wv.w * tv.w;
            }
            ws[t] = d * (1.0f / S_CONST);
        }
        __syncthreads();

        const int lane = t & 31, wid = t >> 5;
        const int rbase = blockIdx.x * 128 + wid * 16;

        float wl[8], bl[8];
#pragma unroll
        for (int q = 0; q < 8; q++) {
            wl[q] = ws[lane + 32 * q];
            bl[q] = b[lane + 32 * q];
        }

        for (int rr = 0; rr < 16; rr++) {
            const int i = rbase + rr;
            const float vi = g_v[i];
            float l[8];
            float m = -CUDART_INF_F;
#pragma unroll
            for (int q = 0; q < 8; q++) {
                l[q] = vi * wl[q] + bl[q];
                m = fmaxf(m, l[q]);
            }
#pragma unroll
            for (int o = 16; o > 0; o >>= 1) m = fmaxf(m, __shfl_xor_sync(0xffffffffu, m, o));
            float sum = 0.f;
#pragma unroll
            for (int q = 0; q < 8; q++) { l[q] = __expf(l[q] - m); sum += l[q]; }
#pragma unroll
            for (int o = 16; o > 0; o >>= 1) sum += __shfl_xor_sync(0xffffffffu, sum, o);
            const float inv = 1.0f / sum;
#pragma unroll
            for (int q = 0; q < 8; q++)
                out[(size_t)i * HID + lane + 32 * q] = l[q] * inv;
        }
    } else {
        // ---- alpha path: one row per block ----
        const int i = blockIdx.x - 64;
        const float a = g_v[i] * (1.0f / S_CONST);
        const float4* v4 = (const float4*)g_v;
        float4* o4 = (float4*)(alpha + (size_t)i * NROWS);
#pragma unroll
        for (int it = 0; it < 8; it++) {
            float4 vv = v4[t + 256 * it];
            o4[t + 256 * it] = make_float4(a * vv.x, a * vv.y, a * vv.z, a * vv.w);
        }
    }
}

// ---------------- launch ---------------------------------------------------
extern "C" void kernel_launch(void* const* d_in, const int* in_sizes, int n_in,
                              void* d_out, int out_size) {
    const float* X  = (const float*)d_in[0];
    const float* E  = (const float*)d_in[1];
    const float* W  = (const float*)d_in[2];
    const float* b  = (const float*)d_in[3];
    const float* Ai = (const float*)d_in[4];
    const float* Aj = (const float*)d_in[5];

    float* out   = (float*)d_out;                       // (8192, 256)
    float* alpha = out + (size_t)NROWS * HID;           // (8192, 8192)

    k_zhe  <<<512, 256>>>(X, W, b, E, Ai, Aj);
    k_v    <<<32, 1024>>>(X);
    k_final<<<64 + NROWS, 256>>>(W, b, out, alpha);
}

// round 13
// speedup vs baseline: 1.2876x; 1.0029x over previous
#include <cuda_runtime.h>
#include <math_constants.h>

#define NROWS 8192
#define IN_DIM 128
#define HID 256
#define SLOPE 0.01f
#define S_CONST 8192.0f

// ---------------- scratch (__device__ globals; no allocs allowed) ----------
__device__ __align__(16) float g_Ppart[32 * 256 * HID];  // [r][kb][c] split-K partials (8 MB)
__device__ __align__(16) float g_v[NROWS];               // normalized flat[:8192]
__device__ __align__(16) float g_Upart[32 * IN_DIM];     // per-v-row partials of v^T X

// ---------------- kernel A (fused): register-tiled GEMM -> Ep partials -----
// grid 512 blocks: kb = bid>>1 (32-row chunk), ch = bid&1 (128-col half).
// 256 threads; thread (ty,tx) owns 4 rows x cols {2tx,2tx+1,2tx+64,2tx+65}.
// W double-buffered in smem [k][col] pitch 130 (float2 reads, conflict-free);
// staging of chunk kc+1 overlaps compute of chunk kc (one sync per chunk).
__global__ void __launch_bounds__(256) k_zhe(
        const float* __restrict__ X, const float* __restrict__ W,
        const float* __restrict__ b, const float* __restrict__ E,
        const float* __restrict__ Ai, const float* __restrict__ Aj) {
    __shared__ float Xs[32 * 132];                // [row][k], pitch 132 (16B-aligned)
    __shared__ __align__(16) float Es[32][32];    // [kk][r]: broadcast float4 reads
    __shared__ __align__(16) float Ws[2][32 * 130]; // W chunk [k][col], double-buffered
    __shared__ float sred[128];
    float* const Hs = &Ws[0][0];                  // aliases buffer 0 after mainloop
    const int t  = threadIdx.x;
    const int tx = t & 31;
    const int ty = t >> 5;                        // 0..7 (constant per warp)
    const int kb = blockIdx.x >> 1;
    const int ch = blockIdx.x & 1;
    const int r0 = kb * 32;                       // row base == E k-chunk base
    const int c0 = ch * 128;                      // column-half base

    if (t < 128) sred[t] = Ai[t] + Aj[t];

    {   // X tile: [row][k], pitch 132 floats; float4 loads/stores
        const float4* X4 = (const float4*)(X + (size_t)r0 * IN_DIM);
        for (int i = t; i < 32 * 32; i += 256) {
            int r = i >> 5, k4 = i & 31;
            *(float4*)&Xs[r * 132 + k4 * 4] = X4[i];
        }
    }
    // E tile: rows 0..31, cols r0..r0+31, layout [kk][r]
    for (int i = t; i < 32 * 32; i += 256) {
        int r = i & 31, kk = i >> 5;
        Es[kk][r] = E[(size_t)r * NROWS + r0 + kk];
    }

    // stage W chunk 0 into buffer 0 (lane tx = k_local; coalesced LDG)
    {
        const float* Wsrc = W + (size_t)c0 * IN_DIM + tx;
#pragma unroll 4
        for (int col = ty; col < 128; col += 8)
            Ws[0][tx * 130 + col] = Wsrc[(size_t)col * IN_DIM];
    }
    __syncthreads();

    // finish s-reduction
    if (t < 64) sred[t] += sred[t + 64];
    __syncthreads();
    if (t < 32) {
        float x = sred[t] + sred[t + 32];
#pragma unroll
        for (int o = 16; o > 0; o >>= 1) x += __shfl_xor_sync(0xffffffffu, x, o);
        if (t == 0) sred[0] = x;
    }
    __syncthreads();
    const float s = sred[0];

    // ---- GEMM mainloop, double-buffered ----
    float acc[4][4];
#pragma unroll
    for (int rr = 0; rr < 4; rr++)
#pragma unroll
        for (int q = 0; q < 4; q++) acc[rr][q] = 0.f;

#pragma unroll 1
    for (int kc = 0; kc < 4; kc++) {
        const int buf = kc & 1;
        if (kc < 3) {   // prefetch next chunk into the other buffer
            const float* Wsrc = W + (size_t)c0 * IN_DIM + (kc + 1) * 32 + tx;
            float* dst = &Ws[buf ^ 1][0];
#pragma unroll 4
            for (int col = ty; col < 128; col += 8)
                dst[tx * 130 + col] = Wsrc[(size_t)col * IN_DIM];
        }

        const float* Wb   = &Ws[buf][0];
        const float* Xrow = Xs + kc * 32;
#pragma unroll 4
        for (int kl = 0; kl < 32; kl += 4) {
            float4 xv[4];
#pragma unroll
            for (int rr = 0; rr < 4; rr++)     // warp-uniform broadcast LDS.128
                xv[rr] = *(const float4*)&Xrow[(ty * 4 + rr) * 132 + kl];

#pragma unroll
            for (int kk = 0; kk < 4; kk++) {
                float2 w0 = *(const float2*)&Wb[(kl + kk) * 130 + 2 * tx];
                float2 w1 = *(const float2*)&Wb[(kl + kk) * 130 + 2 * tx + 64];
#pragma unroll
                for (int rr = 0; rr < 4; rr++) {
                    float xk = (kk == 0) ? xv[rr].x : (kk == 1) ? xv[rr].y
                             : (kk == 2) ? xv[rr].z : xv[rr].w;
                    acc[rr][0] += xk * w0.x;
                    acc[rr][1] += xk * w0.y;
                    acc[rr][2] += xk * w1.x;
                    acc[rr][3] += xk * w1.y;
                }
            }
        }
        __syncthreads();   // chunk consumed; prefetched buffer complete
    }

    // ---- activation; stage h into Hs (aliases Ws buffer 0, pitch 130) ----
    {
        const int cl0 = 2 * tx, cl1 = 2 * tx + 64;
        float b0 = b[c0 + cl0], b1 = b[c0 + cl0 + 1];
        float b2 = b[c0 + cl1], b3 = b[c0 + cl1 + 1];
#pragma unroll
        for (int rr = 0; rr < 4; rr++) {
            const int row = ty * 4 + rr;
            float a0 = (acc[rr][0] + b0) * s;
            float a1 = (acc[rr][1] + b1) * s;
            float a2 = (acc[rr][2] + b2) * s;
            float a3 = (acc[rr][3] + b3) * s;
            a0 = a0 > 0.f ? a0 : SLOPE * a0;
            a1 = a1 > 0.f ? a1 : SLOPE * a1;
            a2 = a2 > 0.f ? a2 : SLOPE * a2;
            a3 = a3 > 0.f ? a3 : SLOPE * a3;
            *(float2*)&Hs[row * 130 + cl0] = make_float2(__expf(a0), __expf(a1));
            *(float2*)&Hs[row * 130 + cl1] = make_float2(__expf(a2), __expf(a3));
        }
    }
    __syncthreads();

    // ---- Ep partial: thread t -> (col = t&127, row-half rh = t>>7) ----
    //   acc2[j] = sum_kk E[16rh+j][r0+kk] * h[kk][c0+col]
    const int col = t & 127;
    const int rh  = t >> 7;          // 0 or 1
    float acc2[16];
#pragma unroll
    for (int j = 0; j < 16; j++) acc2[j] = 0.f;

#pragma unroll 4
    for (int kk = 0; kk < 32; kk++) {
        float h = Hs[kk * 130 + col];            // consecutive lanes: conflict-free
        const float4* es4 = (const float4*)Es[kk] + rh * 4;
#pragma unroll
        for (int j4 = 0; j4 < 4; j4++) {
            float4 e = es4[j4];
            acc2[j4 * 4 + 0] += e.x * h;
            acc2[j4 * 4 + 1] += e.y * h;
            acc2[j4 * 4 + 2] += e.z * h;
            acc2[j4 * 4 + 3] += e.w * h;
        }
    }
#pragma unroll
    for (int j = 0; j < 16; j++)
        g_Ppart[((size_t)(rh * 16 + j) * 256 + kb) * HID + c0 + col] = acc2[j];
}

// ---------------- kernel B: reduce partials -> v; also partial of v^T X ----
// grid 32 blocks (one v-row each), 1024 threads
__global__ void k_v(const float* __restrict__ X) {
    __shared__ float sm[16][256];
    __shared__ float red[256];
    __shared__ float vsm[256];
    __shared__ float su[8][128];
    const int t = threadIdx.x;
    const int r = blockIdx.x;

    {   // phase 1: sum 256 kb-partials (contiguous, float4)
        const float4* P4 = (const float4*)(g_Ppart + (size_t)r * 256 * HID);
        const int c4 = t & 63, y = t >> 6;
        float4 a = make_float4(0.f, 0.f, 0.f, 0.f);
#pragma unroll
        for (int m = 0; m < 16; m++) {
            float4 p = P4[(size_t)(y + 16 * m) * 64 + c4];
            a.x += p.x; a.y += p.y; a.z += p.z; a.w += p.w;
        }
        sm[y][c4 * 4 + 0] = a.x;
        sm[y][c4 * 4 + 1] = a.y;
        sm[y][c4 * 4 + 2] = a.z;
        sm[y][c4 * 4 + 3] = a.w;
    }
    __syncthreads();

    float p = 0.f;
    if (t < 256) {
#pragma unroll
        for (int y = 0; y < 16; y++) p += sm[y][t];
        red[t] = p;
    }
    __syncthreads();
    if (t < 128) red[t] += red[t + 128];
    __syncthreads();
    if (t < 64)  red[t] += red[t + 64];
    __syncthreads();
    if (t < 32) {
        float x = red[t] + red[t + 32];
#pragma unroll
        for (int o = 16; o > 0; o >>= 1) x += __shfl_xor_sync(0xffffffffu, x, o);
        if (t == 0) red[0] = x;
    }
    __syncthreads();
    const float inv = 1.0f / red[0];
    if (t < 256) {
        float v = p * inv;
        vsm[t] = v;
        g_v[r * HID + t] = v;
    }
    __syncthreads();

    {   // phase 2: partial t_r[k] = sum_{c<256} v_c * X[256r + c][k]
        const int k = t & 127, jg = t >> 7;     // jg in [0,8)
        float acc = 0.f;
        const float* Xr = X + ((size_t)r * 256 + jg * 32) * IN_DIM + k;
#pragma unroll
        for (int jj = 0; jj < 32; jj++)
            acc += vsm[jg * 32 + jj] * Xr[(size_t)jj * IN_DIM];
        su[jg][k] = acc;
    }
    __syncthreads();
    if (t < 128) {
        float tot = 0.f;
#pragma unroll
        for (int g = 0; g < 8; g++) tot += su[g][t];
        g_Upart[r * IN_DIM + t] = tot;
    }
}

// ---------------- kernel C (fused): out blocks + alpha blocks --------------
// grid = 64 + 8192, 256 threads.
//   bid < 64   : redundant-w + softmax for 128 rows (hides under alpha's DRAM wall)
//   bid >= 64  : alpha[bid-64,:] = (v_i/S) * v
__global__ void k_final(const float* __restrict__ W, const float* __restrict__ b,
                        float* __restrict__ out, float* __restrict__ alpha) {
    const int t = threadIdx.x;

    if (blockIdx.x < 64) {
        // ---- out path: recompute w from g_Upart (L2-cached), then softmax ----
        __shared__ __align__(16) float ts[128];
        __shared__ float ws[256];

        if (t < 128) {
            float a = 0.f;
#pragma unroll
            for (int rr = 0; rr < 32; rr++) a += g_Upart[rr * IN_DIM + t];
            ts[t] = a;
        }
        __syncthreads();

        {   // w[t] = dot(ts, W[t,:]) / S
            const float4* Wr = (const float4*)(W + (size_t)t * IN_DIM);
            const float4* t4 = (const float4*)ts;
            float d = 0.f;
#pragma unroll
            for (int i = 0; i < 32; i++) {
                float4 wv = Wr[i], tv = t4[i];
                d += wv.x * tv.x + wv.y * tv.y + wv.z * tv.z + wv.w * tv.w;
            }
            ws[t] = d * (1.0f / S_CONST);
        }
        __syncthreads();

        const int lane = t & 31, wid = t >> 5;
        const int rbase = blockIdx.x * 128 + wid * 16;

        float wl[8], bl[8];
#pragma unroll
        for (int q = 0; q < 8; q++) {
            wl[q] = ws[lane + 32 * q];
            bl[q] = b[lane + 32 * q];
        }

        for (int rr = 0; rr < 16; rr++) {
            const int i = rbase + rr;
            const float vi = g_v[i];
            float l[8];
            float m = -CUDART_INF_F;
#pragma unroll
            for (int q = 0; q < 8; q++) {
                l[q] = vi * wl[q] + bl[q];
                m = fmaxf(m, l[q]);
            }
#pragma unroll
            for (int o = 16; o > 0; o >>= 1) m = fmaxf(m, __shfl_xor_sync(0xffffffffu, m, o));
            float sum = 0.f;
#pragma unroll
            for (int q = 0; q < 8; q++) { l[q] = __expf(l[q] - m); sum += l[q]; }
#pragma unroll
            for (int o = 16; o > 0; o >>= 1) sum += __shfl_xor_sync(0xffffffffu, sum, o);
            const float inv = 1.0f / sum;
#pragma unroll
            for (int q = 0; q < 8; q++)
                out[(size_t)i * HID + lane + 32 * q] = l[q] * inv;
        }
    } else {
        // ---- alpha path: one row per block ----
        const int i = blockIdx.x - 64;
        const float a = g_v[i] * (1.0f / S_CONST);
        const float4* v4 = (const float4*)g_v;
        float4* o4 = (float4*)(alpha + (size_t)i * NROWS);
#pragma unroll
        for (int it = 0; it < 8; it++) {
            float4 vv = v4[t + 256 * it];
            o4[t + 256 * it] = make_float4(a * vv.x, a * vv.y, a * vv.z, a * vv.w);
        }
    }
}

// ---------------- launch ---------------------------------------------------
extern "C" void kernel_launch(void* const* d_in, const int* in_sizes, int n_in,
                              void* d_out, int out_size) {
    const float* X  = (const float*)d_in[0];
    const float* E  = (const float*)d_in[1];
    const float* W  = (const float*)d_in[2];
    const float* b  = (const float*)d_in[3];
    const float* Ai = (const float*)d_in[4];
    const float* Aj = (const float*)d_in[5];

    float* out   = (float*)d_out;                       // (8192, 256)
    float* alpha = out + (size_t)NROWS * HID;           // (8192, 8192)

    k_zhe  <<<512, 256>>>(X, W, b, E, Ai, Aj);
    k_v    <<<32, 1024>>>(X);
    k_final<<<64 + NROWS, 256>>>(W, b, out, alpha);
}